// round 6
// baseline (speedup 1.0000x reference)
#include <cuda_runtime.h>
#include <math.h>

#define ESN_B 256
#define ESN_T 512
#define ESN_D 64
#define ESN_U 512
#define ESN_M (ESN_B * ESN_T)   // 131072 drive rows
#define NBLOCKS 128             // persistent scan grid (8 x 16), 1 CTA/SM

// scratch (device globals — allocation-free rule). Indexed [b*T*U + t*U + u].
__device__ float g_u [(size_t)ESN_M * ESN_U];   // input drive  [B,T,U]
__device__ float g_st[(size_t)ESN_M * ESN_U];   // layer states [B,T,U]
__device__ float g_hA[ESN_B * ESN_U];           // ping-pong state
__device__ float g_hB[ESN_B * ESN_U];
__device__ float g_r [ESN_B * 3 * ESN_U];       // concat of last states

// software grid barrier state (generation counter; replay-safe: gen is
// monotonic, cnt returns to 0 after every barrier)
__device__ unsigned g_bar_gen = 0;
__device__ unsigned g_bar_cnt = 0;

__device__ __forceinline__ void grid_barrier() {
    __syncthreads();
    if (threadIdx.x == 0) {
        __threadfence();                       // publish this CTA's stores
        volatile unsigned* genp = &g_bar_gen;
        unsigned my = *genp;
        if (atomicAdd(&g_bar_cnt, 1u) == NBLOCKS - 1u) {
            atomicExch(&g_bar_cnt, 0u);        // reset before release
            __threadfence();
            atomicAdd(&g_bar_gen, 1u);         // release
        } else {
            while (*genp == my) { }
        }
        __threadfence();                       // acquire peers' stores
    }
    __syncthreads();
}

// accurate even if the build swaps expf for __expf (~5e-7 rel); avoids the
// low-precision HW tanh path that could blow the 1e-3 gate after 512 steps.
__device__ __forceinline__ float tanh_f(float x) {
    return 1.0f - 2.0f / (expf(2.0f * x) + 1.0f);
}

// ---------------------------------------------------------------------------
// Drive GEMM: g_u[M,512] = A[M,K] @ W[K,512] + bias.
// 128x64x32 tiles, 256 threads, 4x8 per-thread micro-tile.
// ---------------------------------------------------------------------------
__global__ __launch_bounds__(256) void drive_gemm(
    const float* __restrict__ A_ext, int use_st,
    const float* __restrict__ W, const float* __restrict__ bias, int K)
{
    const float* __restrict__ A = use_st ? (const float*)g_st : A_ext;
    __shared__ float As[128 * 33];
    __shared__ float Bs[32 * 68];
    const int m0 = blockIdx.x * 128, n0 = blockIdx.y * 64;
    const int t = threadIdx.x;
    const int rowg = t >> 3, colg = t & 7;
    float acc[4][8] = {};

    for (int k0 = 0; k0 < K; k0 += 32) {
        #pragma unroll
        for (int i = 0; i < 16; i++) {                // A tile 128x32
            int idx = t + i * 256, m = idx >> 5, k = idx & 31;
            As[m * 33 + k] = A[(size_t)(m0 + m) * K + k0 + k];
        }
        #pragma unroll
        for (int i = 0; i < 8; i++) {                 // W tile 32x64
            int idx = t + i * 256, k = idx >> 6, c = idx & 63;
            Bs[k * 68 + c] = W[(size_t)(k0 + k) * ESN_U + n0 + c];
        }
        __syncthreads();
        #pragma unroll 8
        for (int kk = 0; kk < 32; kk++) {
            float a[4];
            #pragma unroll
            for (int i = 0; i < 4; i++) a[i] = As[(rowg * 4 + i) * 33 + kk];
            float4 bA = *(const float4*)&Bs[kk * 68 + colg * 8];
            float4 bB = *(const float4*)&Bs[kk * 68 + colg * 8 + 4];
            #pragma unroll
            for (int i = 0; i < 4; i++) {
                acc[i][0] += a[i] * bA.x; acc[i][1] += a[i] * bA.y;
                acc[i][2] += a[i] * bA.z; acc[i][3] += a[i] * bA.w;
                acc[i][4] += a[i] * bB.x; acc[i][5] += a[i] * bB.y;
                acc[i][6] += a[i] * bB.z; acc[i][7] += a[i] * bB.w;
            }
        }
        __syncthreads();
    }
    float4 biA = *(const float4*)&bias[n0 + colg * 8];
    float4 biB = *(const float4*)&bias[n0 + colg * 8 + 4];
    #pragma unroll
    for (int i = 0; i < 4; i++) {
        size_t off = (size_t)(m0 + rowg * 4 + i) * ESN_U + n0 + colg * 8;
        *(float4*)&g_u[off]     = make_float4(acc[i][0]+biA.x, acc[i][1]+biA.y,
                                              acc[i][2]+biA.z, acc[i][3]+biA.w);
        *(float4*)&g_u[off + 4] = make_float4(acc[i][4]+biB.x, acc[i][5]+biB.y,
                                              acc[i][6]+biB.z, acc[i][7]+biB.w);
    }
}

// ---------------------------------------------------------------------------
// Persistent recurrent scan (one launch per layer, all T steps in-kernel):
//   h' = 0.1*h + 0.9*tanh(u_t + h @ Wrec)
// Grid (8,16): 32x32 output tiles, 1 CTA/SM (172KB smem), all 128 resident.
// Wrec column-slice staged ONCE; per step: stage h (per-warp private k-slice,
// __syncwarp only), 8-warp k-split 4x8 micro-tile compute, smem cross-warp
// reduce, fused leak/tanh epilogue, software grid barrier.
// ---------------------------------------------------------------------------
#define HS_STRIDE 513
#define WS_STRIDE 36
#define SM_HS (32 * HS_STRIDE)                 // 16416 words
#define SM_WS (512 * WS_STRIDE)                // 18432 words
#define SM_RED (8 * 1024)                      // 8192 words
#define STEP_SMEM_BYTES ((SM_HS + SM_WS + SM_RED) * 4)   // 172160 B

__global__ __launch_bounds__(256, 1) void esn_scan(
    const float* __restrict__ W, int store_states, int layer)
{
    extern __shared__ float smem[];
    float* hs  = smem;                 // [32][513]: h rows, all 512 feats
    float* ws  = smem + SM_HS;         // [512][36]: Wrec col slice (resident)
    float* red = smem + SM_HS + SM_WS; // [8][1024]: cross-warp partials

    const int row0 = blockIdx.x * 32, col0 = blockIdx.y * 32;
    const int t = threadIdx.x, w = t >> 5, lane = t & 31;
    const int kbase = w * 64;
    const int lane_r = lane >> 2, lane_c = lane & 3;
    const size_t bstride = (size_t)ESN_T * ESN_U;

    // --- one-time staging: Wrec slice + zero hs (serves as h(0)=0) ---
    for (int i = lane; i < 512; i += 32) {            // W: 64 k x 32 cols
        int kk = i >> 3, c4 = (i & 7) << 2;
        *(float4*)&ws[(kbase + kk) * WS_STRIDE + c4] =
            *(const float4*)&W[(size_t)(kbase + kk) * ESN_U + col0 + c4];
    }
    for (int i = t; i < SM_HS; i += 256) hs[i] = 0.0f;
    __syncthreads();

    const float* wsk = ws + (size_t)kbase * WS_STRIDE + lane_c * 8;
    const float* hsk = hs + lane_r * 4 * HS_STRIDE + kbase;

    for (int tt = 0; tt < ESN_T; tt++) {
        if (tt > 0) {                                 // stage h (own k-slice)
            const float* __restrict__ h_in = (tt & 1) ? (const float*)g_hB
                                                      : (const float*)g_hA;
            for (int i = lane; i < 512; i += 32) {    // 32 rows x 64 k
                int rr = i >> 4, k4 = (i & 15) << 2;
                float4 v = *(const float4*)&h_in[(size_t)(row0 + rr) * ESN_U + kbase + k4];
                float* d = &hs[rr * HS_STRIDE + kbase + k4];
                d[0] = v.x; d[1] = v.y; d[2] = v.z; d[3] = v.w;
            }
            __syncwarp();
        }

        float acc[4][8] = {};
        #pragma unroll 4
        for (int kk = 0; kk < 64; kk++) {
            float4 bA = *(const float4*)(wsk + kk * WS_STRIDE);
            float4 bB = *(const float4*)(wsk + kk * WS_STRIDE + 4);
            float a[4];
            #pragma unroll
            for (int i = 0; i < 4; i++) a[i] = hsk[i * HS_STRIDE + kk];
            #pragma unroll
            for (int i = 0; i < 4; i++) {
                acc[i][0] += a[i] * bA.x; acc[i][1] += a[i] * bA.y;
                acc[i][2] += a[i] * bA.z; acc[i][3] += a[i] * bA.w;
                acc[i][4] += a[i] * bB.x; acc[i][5] += a[i] * bB.y;
                acc[i][6] += a[i] * bB.z; acc[i][7] += a[i] * bB.w;
            }
        }
        #pragma unroll
        for (int i = 0; i < 4; i++) {
            int base = w * 1024 + (lane_r * 4 + i) * 32 + lane_c * 8;
            *(float4*)&red[base]     = make_float4(acc[i][0], acc[i][1], acc[i][2], acc[i][3]);
            *(float4*)&red[base + 4] = make_float4(acc[i][4], acc[i][5], acc[i][6], acc[i][7]);
        }
        __syncthreads();

        // epilogue: 4 consecutive outputs per thread
        const int rr = t >> 3, cb = (t & 7) << 2;
        float4 s = *(const float4*)&red[rr * 32 + cb];
        #pragma unroll
        for (int ww = 1; ww < 8; ww++) {
            float4 p = *(const float4*)&red[ww * 1024 + rr * 32 + cb];
            s.x += p.x; s.y += p.y; s.z += p.z; s.w += p.w;
        }
        const size_t urow = (size_t)(row0 + rr) * bstride + (size_t)tt * ESN_U + col0 + cb;
        float4 uu = *(const float4*)&g_u[urow];
        float h0 = hs[rr * HS_STRIDE + col0 + cb + 0];
        float h1 = hs[rr * HS_STRIDE + col0 + cb + 1];
        float h2 = hs[rr * HS_STRIDE + col0 + cb + 2];
        float h3 = hs[rr * HS_STRIDE + col0 + cb + 3];
        float4 o = make_float4(0.1f * h0 + 0.9f * tanh_f(uu.x + s.x),
                               0.1f * h1 + 0.9f * tanh_f(uu.y + s.y),
                               0.1f * h2 + 0.9f * tanh_f(uu.z + s.z),
                               0.1f * h3 + 0.9f * tanh_f(uu.w + s.w));
        float* __restrict__ h_out = (tt & 1) ? g_hA : g_hB;
        *(float4*)&h_out[(size_t)(row0 + rr) * ESN_U + col0 + cb] = o;
        if (store_states)
            *(float4*)&g_st[urow] = o;
        if (tt == ESN_T - 1)                           // fold copy_h
            *(float4*)&g_r[(size_t)(row0 + rr) * 1536 + layer * 512 + col0 + cb] = o;

        if (tt < ESN_T - 1) grid_barrier();
    }
}

// ---------------------------------------------------------------------------
__global__ __launch_bounds__(256) void readout(
    const float* __restrict__ Wout, const float* __restrict__ bout,
    float* __restrict__ out)
{
    const int b = blockIdx.x;
    float acc[10] = {};
    for (int j = threadIdx.x; j < 3 * ESN_U; j += 256) {
        float v = g_r[(size_t)b * 1536 + j];
        #pragma unroll
        for (int c = 0; c < 10; c++) acc[c] += v * Wout[j * 10 + c];
    }
    __shared__ float sm[8][10];
    const int w = threadIdx.x >> 5, lane = threadIdx.x & 31;
    #pragma unroll
    for (int c = 0; c < 10; c++) {
        float v = acc[c];
        #pragma unroll
        for (int o = 16; o > 0; o >>= 1) v += __shfl_down_sync(0xffffffffu, v, o);
        if (lane == 0) sm[w][c] = v;
    }
    __syncthreads();
    if (threadIdx.x < 10) {
        float s = bout[threadIdx.x];
        #pragma unroll
        for (int ww = 0; ww < 8; ww++) s += sm[ww][threadIdx.x];
        out[b * 10 + threadIdx.x] = s;
    }
}

// ---------------------------------------------------------------------------
extern "C" void kernel_launch(void* const* d_in, const int* in_sizes, int n_in,
                              void* d_out, int out_size)
{
    (void)in_sizes; (void)n_in; (void)out_size;
    const float* x       = (const float*)d_in[0];
    const float* Wins[3] = {(const float*)d_in[1], (const float*)d_in[4], (const float*)d_in[7]};
    const float* Wrec[3] = {(const float*)d_in[2], (const float*)d_in[5], (const float*)d_in[8]};
    const float* bias[3] = {(const float*)d_in[3], (const float*)d_in[6], (const float*)d_in[9]};
    const float* Wout    = (const float*)d_in[10];
    const float* bout    = (const float*)d_in[11];
    float* out = (float*)d_out;

    cudaFuncSetAttribute(esn_scan, cudaFuncAttributeMaxDynamicSharedMemorySize,
                         STEP_SMEM_BYTES);

    for (int l = 0; l < 3; l++) {
        const int K = (l == 0) ? ESN_D : ESN_U;
        drive_gemm<<<dim3(ESN_M / 128, ESN_U / 64), 256>>>(
            x, (l == 0) ? 0 : 1, Wins[l], bias[l], K);
        esn_scan<<<dim3(8, 16), 256, STEP_SMEM_BYTES>>>(
            Wrec[l], (l < 2) ? 1 : 0, l);
    }
    readout<<<ESN_B, 256>>>(Wout, bout, out);
}

// round 13
// speedup vs baseline: 1.4509x; 1.4509x over previous
#include <cuda_runtime.h>
#include <cuda_bf16.h>
#include <math.h>

#define ESN_B 256
#define ESN_T 512
#define ESN_D 64
#define ESN_U 512
#define ESN_M (ESN_B * ESN_T)   // 131072 drive rows
#define NBLOCKS 128             // persistent scan grid (8 x 16), 1 CTA/SM

// scratch (device globals — allocation-free rule). Indexed [b*T*U + t*U + u].
__device__ float    g_u [(size_t)ESN_M * ESN_U];  // input drive  [B,T,U]
__device__ float    g_st[(size_t)ESN_M * ESN_U];  // layer states [B,T,U]
__device__ unsigned g_hPA[ESN_B * ESN_U];         // ping-pong h, packed bf16 hi|lo<<16
__device__ unsigned g_hPB[ESN_B * ESN_U];
__device__ float    g_r [ESN_B * 3 * ESN_U];      // concat of last states

// software grid barrier (generation counter; replay-safe: gen monotonic,
// cnt returns to 0 after every barrier). Validated in Round 6.
__device__ unsigned g_bar_gen = 0;
__device__ unsigned g_bar_cnt = 0;

__device__ __forceinline__ void grid_barrier() {
    __syncthreads();
    if (threadIdx.x == 0) {
        __threadfence();
        volatile unsigned* genp = &g_bar_gen;
        unsigned my = *genp;
        if (atomicAdd(&g_bar_cnt, 1u) == NBLOCKS - 1u) {
            atomicExch(&g_bar_cnt, 0u);
            __threadfence();
            atomicAdd(&g_bar_gen, 1u);
        } else {
            while (*genp == my) { }
        }
        __threadfence();
    }
    __syncthreads();
}

// accurate even if the build swaps expf for __expf (~5e-7 rel)
__device__ __forceinline__ float tanh_f(float x) {
    return 1.0f - 2.0f / (expf(2.0f * x) + 1.0f);
}

// bf16 hi/lo split pack: low 16 = bf16(v), high 16 = bf16(v - hi)
__device__ __forceinline__ unsigned pack_split(float v) {
    __nv_bfloat16 h = __float2bfloat16(v);
    float r = v - __bfloat162float(h);
    __nv_bfloat16 l = __float2bfloat16(r);
    return (unsigned)__bfloat16_as_ushort(h) |
           ((unsigned)__bfloat16_as_ushort(l) << 16);
}
__device__ __forceinline__ void split2(float v, unsigned short& h, unsigned short& l) {
    __nv_bfloat16 bh = __float2bfloat16(v);
    h = __bfloat16_as_ushort(bh);
    l = __bfloat16_as_ushort(__float2bfloat16(v - __bfloat162float(bh)));
}
__device__ __forceinline__ float bfbits2f(unsigned short b) {
    return __uint_as_float(((unsigned)b) << 16);   // exact bf16->fp32
}

__device__ __forceinline__ unsigned smaddr(const void* p) {
    return (unsigned)__cvta_generic_to_shared(p);
}
__device__ __forceinline__ void ldsm_x4(unsigned& r0, unsigned& r1,
                                        unsigned& r2, unsigned& r3, unsigned a) {
    asm volatile("ldmatrix.sync.aligned.m8n8.x4.shared.b16 {%0,%1,%2,%3}, [%4];"
                 : "=r"(r0), "=r"(r1), "=r"(r2), "=r"(r3) : "r"(a));
}
__device__ __forceinline__ void ldsm_x4_t(unsigned& r0, unsigned& r1,
                                          unsigned& r2, unsigned& r3, unsigned a) {
    asm volatile("ldmatrix.sync.aligned.m8n8.x4.trans.shared.b16 {%0,%1,%2,%3}, [%4];"
                 : "=r"(r0), "=r"(r1), "=r"(r2), "=r"(r3) : "r"(a));
}
__device__ __forceinline__ void ldsm_x2(unsigned& r0, unsigned& r1, unsigned a) {
    asm volatile("ldmatrix.sync.aligned.m8n8.x2.shared.b16 {%0,%1}, [%2];"
                 : "=r"(r0), "=r"(r1) : "r"(a));
}
__device__ __forceinline__ void mma_bf16(float& d0, float& d1, float& d2, float& d3,
                                         unsigned a0, unsigned a1, unsigned a2, unsigned a3,
                                         unsigned b0, unsigned b1) {
    asm volatile(
        "mma.sync.aligned.m16n8k16.row.col.f32.bf16.bf16.f32 "
        "{%0,%1,%2,%3}, {%4,%5,%6,%7}, {%8,%9}, {%0,%1,%2,%3};"
        : "+f"(d0), "+f"(d1), "+f"(d2), "+f"(d3)
        : "r"(a0), "r"(a1), "r"(a2), "r"(a3), "r"(b0), "r"(b1));
}

// ---------------------------------------------------------------------------
// Drive GEMM via bf16 hi/lo split MMA: g_u[M,512] = A[M,K] @ W[K,512] + bias.
// CTA 128x64, 8 warps (4 m x 2 n), warp tile 32x32 = 2(m16) x 4(n8).
// K chunked by 64. A smem row-major [128][72] hi/lo (144B stride -> 4-bank
// ldmatrix advance, conflict-free). W smem k-major [64][72] hi/lo, B frags
// via ldmatrix.x4.trans (matrices (m0,m1)=k0-7/k8-15 for first n8, (m2,m3)
// for second n8 = exactly the .col B fragments).
// ---------------------------------------------------------------------------
#define DRV_SMEM_BYTES (27648 * 2)   // 55296 B (A:2x9216 + W:2x4608 ushorts)

__global__ __launch_bounds__(256, 2) void drive_gemm_mma(
    const float* __restrict__ A_ext, int use_st,
    const float* __restrict__ W, const float* __restrict__ bias, int K)
{
    const float* __restrict__ A = use_st ? (const float*)g_st : A_ext;
    extern __shared__ unsigned short ds[];
    unsigned short* A_hi = ds;             // [128][72]
    unsigned short* A_lo = ds + 9216;
    unsigned short* W_hi = ds + 18432;     // [64][72], k-major
    unsigned short* W_lo = ds + 23040;

    const int m0 = blockIdx.x * 128, n0 = blockIdx.y * 64;
    const int t = threadIdx.x, w = t >> 5, lane = t & 31;
    const int warp_m = (w & 3) * 32, warp_n = (w >> 2) * 32;

    // ldmatrix lane addresses
    const int lr = lane & 15, lc = lane >> 4;
    unsigned aAH[2], aAL[2], bAH[2], bAL[2];
    #pragma unroll
    for (int mt = 0; mt < 2; mt++) {
        aAH[mt] = smaddr(&A_hi[(warp_m + mt * 16 + lr) * 72 + lc * 8]);
        aAL[mt] = smaddr(&A_lo[(warp_m + mt * 16 + lr) * 72 + lc * 8]);
    }
    #pragma unroll
    for (int g = 0; g < 2; g++) {          // n-groups: tiles {2g, 2g+1}
        bAH[g] = smaddr(&W_hi[lr * 72 + warp_n + g * 16 + lc * 8]);
        bAL[g] = smaddr(&W_lo[lr * 72 + warp_n + g * 16 + lc * 8]);
    }

    const int srow = t >> 4, scol = (t & 15) * 4;   // staging: float4 lanes
    float acc[2][4][4] = {};

    for (int k0 = 0; k0 < K; k0 += 64) {
        #pragma unroll
        for (int i = 0; i < 8; i++) {                 // A chunk: 128 x 64
            int row = srow + i * 16;
            float4 v = *(const float4*)&A[(size_t)(m0 + row) * K + k0 + scol];
            unsigned short h0,h1,h2,h3,l0,l1,l2,l3;
            split2(v.x,h0,l0); split2(v.y,h1,l1); split2(v.z,h2,l2); split2(v.w,h3,l3);
            *(ushort2*)&A_hi[row * 72 + scol]     = make_ushort2(h0, h1);
            *(ushort2*)&A_hi[row * 72 + scol + 2] = make_ushort2(h2, h3);
            *(ushort2*)&A_lo[row * 72 + scol]     = make_ushort2(l0, l1);
            *(ushort2*)&A_lo[row * 72 + scol + 2] = make_ushort2(l2, l3);
        }
        #pragma unroll
        for (int i = 0; i < 4; i++) {                 // W chunk: 64 k x 64 n
            int kk = srow + i * 16;
            float4 v = *(const float4*)&W[(size_t)(k0 + kk) * ESN_U + n0 + scol];
            unsigned short h0,h1,h2,h3,l0,l1,l2,l3;
            split2(v.x,h0,l0); split2(v.y,h1,l1); split2(v.z,h2,l2); split2(v.w,h3,l3);
            *(ushort2*)&W_hi[kk * 72 + scol]     = make_ushort2(h0, h1);
            *(ushort2*)&W_hi[kk * 72 + scol + 2] = make_ushort2(h2, h3);
            *(ushort2*)&W_lo[kk * 72 + scol]     = make_ushort2(l0, l1);
            *(ushort2*)&W_lo[kk * 72 + scol + 2] = make_ushort2(l2, l3);
        }
        __syncthreads();

        #pragma unroll
        for (int ks = 0; ks < 4; ks++) {
            const unsigned aOff = ks * 32;            // +16 k cols = 32 B
            const unsigned bOff = ks * 2304;          // +16 k rows = 16*144 B
            unsigned ah[2][4], al[2][4], bh[4][2], bl[4][2];
            #pragma unroll
            for (int mt = 0; mt < 2; mt++) {
                ldsm_x4(ah[mt][0], ah[mt][1], ah[mt][2], ah[mt][3], aAH[mt] + aOff);
                ldsm_x4(al[mt][0], al[mt][1], al[mt][2], al[mt][3], aAL[mt] + aOff);
            }
            #pragma unroll
            for (int g = 0; g < 2; g++) {
                ldsm_x4_t(bh[2*g][0], bh[2*g][1], bh[2*g+1][0], bh[2*g+1][1], bAH[g] + bOff);
                ldsm_x4_t(bl[2*g][0], bl[2*g][1], bl[2*g+1][0], bl[2*g+1][1], bAL[g] + bOff);
            }
            #pragma unroll
            for (int mt = 0; mt < 2; mt++)
                #pragma unroll
                for (int nt = 0; nt < 4; nt++) {
                    mma_bf16(acc[mt][nt][0], acc[mt][nt][1], acc[mt][nt][2], acc[mt][nt][3],
                             ah[mt][0], ah[mt][1], ah[mt][2], ah[mt][3], bh[nt][0], bh[nt][1]);
                    mma_bf16(acc[mt][nt][0], acc[mt][nt][1], acc[mt][nt][2], acc[mt][nt][3],
                             ah[mt][0], ah[mt][1], ah[mt][2], ah[mt][3], bl[nt][0], bl[nt][1]);
                    mma_bf16(acc[mt][nt][0], acc[mt][nt][1], acc[mt][nt][2], acc[mt][nt][3],
                             al[mt][0], al[mt][1], al[mt][2], al[mt][3], bh[nt][0], bh[nt][1]);
                }
        }
        __syncthreads();
    }

    // epilogue: D frag row = l>>2 (+8), col = 2*(l&3); add bias, write fp32
    const int erow = lane >> 2, ecol = (lane & 3) * 2;
    #pragma unroll
    for (int mt = 0; mt < 2; mt++)
        #pragma unroll
        for (int nt = 0; nt < 4; nt++) {
            int c = n0 + warp_n + nt * 8 + ecol;
            float b0 = bias[c], b1 = bias[c + 1];
            int r = m0 + warp_m + mt * 16 + erow;
            *(float2*)&g_u[(size_t)r * ESN_U + c] =
                make_float2(acc[mt][nt][0] + b0, acc[mt][nt][1] + b1);
            *(float2*)&g_u[(size_t)(r + 8) * ESN_U + c] =
                make_float2(acc[mt][nt][2] + b0, acc[mt][nt][3] + b1);
        }
}

// ---------------------------------------------------------------------------
// Persistent tensor-core scan: h' = 0.1*h + 0.9*tanh(u_t + h @ Wrec)
// via bf16 hi/lo split (3 MMAs), fp32 accumulate. UNCHANGED from audited R7.
// ---------------------------------------------------------------------------
#define HPAD 520
#define SCAN_SMEM_BYTES (4 * 32 * HPAD * 2)   // 133120 B

__global__ __launch_bounds__(256, 1) void esn_scan_mma(
    const float* __restrict__ W, int store_states, int layer)
{
    extern __shared__ unsigned short sm[];
    unsigned short* h_hi  = sm;
    unsigned short* h_lo  = sm + 32 * HPAD;
    unsigned short* wt_hi = sm + 2 * 32 * HPAD;
    unsigned short* wt_lo = sm + 3 * 32 * HPAD;

    const int row0 = blockIdx.x * 32, col0 = blockIdx.y * 32;
    const int tid = threadIdx.x, w = tid >> 5, lane = tid & 31;
    const int m_tile = w & 1, n_tile = w >> 1;            // 2 x 4 warp tiles
    const size_t bstride = (size_t)ESN_T * ESN_U;

    for (int i = tid; i < 2 * 32 * HPAD; i += 256) sm[i] = 0;

    {
        const int n = tid & 31, kb = (tid >> 5) * 64;
        for (int k = 0; k < 64; k++) {
            float wv = W[(size_t)(kb + k) * ESN_U + col0 + n];
            __nv_bfloat16 hi = __float2bfloat16(wv);
            float lof = wv - __bfloat162float(hi);
            wt_hi[n * HPAD + kb + k] = __bfloat16_as_ushort(hi);
            wt_lo[n * HPAD + kb + k] = __bfloat16_as_ushort(__float2bfloat16(lof));
        }
    }
    __syncthreads();

    const int aRow = m_tile * 16 + (lane & 15);
    const int aCol = (lane >> 4) << 3;
    const unsigned aHiA = smaddr(&h_hi[aRow * HPAD + aCol]);
    const unsigned aLoA = smaddr(&h_lo[aRow * HPAD + aCol]);
    const int bRow = n_tile * 8 + (lane & 7);
    const int bCol = (lane & 8) ? 8 : 0;
    const unsigned bHiA = smaddr(&wt_hi[bRow * HPAD + bCol]);
    const unsigned bLoA = smaddr(&wt_lo[bRow * HPAD + bCol]);

    const int srow = tid >> 3, sa = tid & 7;
    const int g = lane >> 2, tg = lane & 3;
    const int ocol  = col0 + n_tile * 8 + tg * 2;
    const int lrow0 = m_tile * 16 + g;

    for (int tt = 0; tt < ESN_T; tt++) {
        if (tt > 0) {
            const unsigned* __restrict__ hin = (tt & 1) ? g_hPB : g_hPA;
            const unsigned* src = &hin[(size_t)(row0 + srow) * ESN_U + sa * 64];
            unsigned short* dh = &h_hi[srow * HPAD + sa * 64];
            unsigned short* dl = &h_lo[srow * HPAD + sa * 64];
            #pragma unroll
            for (int js = 0; js < 16; js++) {
                int jj = js ^ (sa << 1);
                uint4 p = *(const uint4*)&src[jj * 4];
                *(ushort2*)&dh[jj * 4]     = make_ushort2((unsigned short)p.x,
                                                          (unsigned short)p.y);
                *(ushort2*)&dh[jj * 4 + 2] = make_ushort2((unsigned short)p.z,
                                                          (unsigned short)p.w);
                *(ushort2*)&dl[jj * 4]     = make_ushort2((unsigned short)(p.x >> 16),
                                                          (unsigned short)(p.y >> 16));
                *(ushort2*)&dl[jj * 4 + 2] = make_ushort2((unsigned short)(p.z >> 16),
                                                          (unsigned short)(p.w >> 16));
            }
        }
        __syncthreads();

        float d0 = 0.f, d1 = 0.f, d2 = 0.f, d3 = 0.f;
        #pragma unroll 8
        for (int kk = 0; kk < 32; kk++) {
            const unsigned off = kk * 32;
            unsigned ah0, ah1, ah2, ah3, al0, al1, al2, al3, bh0, bh1, bl0, bl1;
            ldsm_x4(ah0, ah1, ah2, ah3, aHiA + off);
            ldsm_x4(al0, al1, al2, al3, aLoA + off);
            ldsm_x2(bh0, bh1, bHiA + off);
            ldsm_x2(bl0, bl1, bLoA + off);
            mma_bf16(d0, d1, d2, d3, ah0, ah1, ah2, ah3, bh0, bh1);
            mma_bf16(d0, d1, d2, d3, ah0, ah1, ah2, ah3, bl0, bl1);
            mma_bf16(d0, d1, d2, d3, al0, al1, al2, al3, bh0, bh1);
        }

        unsigned* __restrict__ hpout = (tt & 1) ? g_hPA : g_hPB;
        #pragma unroll
        for (int half = 0; half < 2; half++) {
            const int lr = lrow0 + half * 8;
            const int r  = row0 + lr;
            const float x = half ? d2 : d0;
            const float y = half ? d3 : d1;
            const size_t upos = (size_t)r * bstride + (size_t)tt * ESN_U + ocol;
            float2 uu = *(const float2*)&g_u[upos];
            float ho0 = bfbits2f(h_hi[lr * HPAD + ocol])     + bfbits2f(h_lo[lr * HPAD + ocol]);
            float ho1 = bfbits2f(h_hi[lr * HPAD + ocol + 1]) + bfbits2f(h_lo[lr * HPAD + ocol + 1]);
            float o0 = 0.1f * ho0 + 0.9f * tanh_f(uu.x + x);
            float o1 = 0.1f * ho1 + 0.9f * tanh_f(uu.y + y);
            *(uint2*)&hpout[(size_t)r * ESN_U + ocol] =
                make_uint2(pack_split(o0), pack_split(o1));
            if (store_states)
                *(float2*)&g_st[upos] = make_float2(o0, o1);
            if (tt == ESN_T - 1)
                *(float2*)&g_r[(size_t)r * 1536 + layer * 512 + ocol] =
                    make_float2(o0, o1);
        }

        if (tt < ESN_T - 1) grid_barrier();
    }
}

// ---------------------------------------------------------------------------
__global__ __launch_bounds__(256) void readout(
    const float* __restrict__ Wout, const float* __restrict__ bout,
    float* __restrict__ out)
{
    const int b = blockIdx.x;
    float acc[10] = {};
    for (int j = threadIdx.x; j < 3 * ESN_U; j += 256) {
        float v = g_r[(size_t)b * 1536 + j];
        #pragma unroll
        for (int c = 0; c < 10; c++) acc[c] += v * Wout[j * 10 + c];
    }
    __shared__ float smr[8][10];
    const int w = threadIdx.x >> 5, lane = threadIdx.x & 31;
    #pragma unroll
    for (int c = 0; c < 10; c++) {
        float v = acc[c];
        #pragma unroll
        for (int o = 16; o > 0; o >>= 1) v += __shfl_down_sync(0xffffffffu, v, o);
        if (lane == 0) smr[w][c] = v;
    }
    __syncthreads();
    if (threadIdx.x < 10) {
        float s = bout[threadIdx.x];
        #pragma unroll
        for (int ww = 0; ww < 8; ww++) s += smr[ww][threadIdx.x];
        out[b * 10 + threadIdx.x] = s;
    }
}

// ---------------------------------------------------------------------------
extern "C" void kernel_launch(void* const* d_in, const int* in_sizes, int n_in,
                              void* d_out, int out_size)
{
    (void)in_sizes; (void)n_in; (void)out_size;
    const float* x       = (const float*)d_in[0];
    const float* Wins[3] = {(const float*)d_in[1], (const float*)d_in[4], (const float*)d_in[7]};
    const float* Wrec[3] = {(const float*)d_in[2], (const float*)d_in[5], (const float*)d_in[8]};
    const float* bias[3] = {(const float*)d_in[3], (const float*)d_in[6], (const float*)d_in[9]};
    const float* Wout    = (const float*)d_in[10];
    const float* bout    = (const float*)d_in[11];
    float* out = (float*)d_out;

    cudaFuncSetAttribute(esn_scan_mma, cudaFuncAttributeMaxDynamicSharedMemorySize,
                         SCAN_SMEM_BYTES);
    cudaFuncSetAttribute(drive_gemm_mma, cudaFuncAttributeMaxDynamicSharedMemorySize,
                         DRV_SMEM_BYTES);

    for (int l = 0; l < 3; l++) {
        const int K = (l == 0) ? ESN_D : ESN_U;
        drive_gemm_mma<<<dim3(ESN_M / 128, ESN_U / 64), 256, DRV_SMEM_BYTES>>>(
            x, (l == 0) ? 0 : 1, Wins[l], bias[l], K);
        esn_scan_mma<<<dim3(8, 16), 256, SCAN_SMEM_BYTES>>>(
            Wrec[l], (l < 2) ? 1 : 0, l);
    }
    readout<<<ESN_B, 256>>>(Wout, bout, out);
}